// round 3
// baseline (speedup 1.0000x reference)
#include <cuda_runtime.h>
#include <cuda_fp16.h>
#include <cstdint>

#define BB 4
#define NN 2048
#define KK 32
#define CIN 16
#define COUT 32
#define HH 32
#define RTOT (BB*NN*KK)      // 262144
#define MTOT (BB*NN)         // 8192
#define EPS 1e-5f
#define FULLMASK 0xffffffffu

// Q layout: [m][o][jp] with jp padded 17->20 half2 (80B rows, 16B aligned)
#define QJP 20
#define QROW (32*QJP)        // 640 half2 per m

// ---------------- scratch ----------------
__device__ __align__(16) float   g_h2[(size_t)RTOT*HH];      // 32 MB (BN2-pre h2)
__device__ __align__(16) __half2 g_Qh[(size_t)MTOT*QROW];    // 20 MB
__device__ int   g_idx[RTOT];
__device__ float g_ps [32*1024];
__device__ float g_ps2[32*1024];
__device__ float g_sc2[64];
__device__ float g_sc3[64];
__device__ __align__(16) float g_W2f[1024];   // sc1-folded W2
__device__ float g_b2f[32];                   // sh1-folded b2

// ---------------- helpers ----------------
__device__ __forceinline__ unsigned long long pack2(float x, float y) {
    unsigned long long r;
    asm("mov.b64 %0, {%1,%2};" : "=l"(r) : "f"(x), "f"(y));
    return r;
}
__device__ __forceinline__ float2 unpack2(unsigned long long v) {
    float2 r;
    asm("mov.b64 {%0,%1}, %2;" : "=f"(r.x), "=f"(r.y) : "l"(v));
    return r;
}
__device__ __forceinline__ unsigned long long ffma2(unsigned long long a, unsigned long long b, unsigned long long c) {
    unsigned long long d;
    asm("fma.rn.f32x2 %0, %1, %2, %3;" : "=l"(d) : "l"(a), "l"(b), "l"(c));
    return d;
}

// warp transpose-reduce: acc[32] per-lane channel values -> acc[0] = sum over lanes of channel `lane`
__device__ __forceinline__ void tr32(float (&acc)[32], int lane) {
#pragma unroll
    for (int s = 16; s >= 1; s >>= 1) {
#pragma unroll
        for (int i = 0; i < s; i++) {
            float a0 = acc[i], a1 = acc[i + s];
            float give = (lane & s) ? a0 : a1;
            float keep = (lane & s) ? a1 : a0;
            acc[i] = keep + __shfl_xor_sync(FULLMASK, give, s);
        }
    }
}

// ---------------- KNN: warp bitonic top-32 ----------------
__device__ __forceinline__ void cas_pair(float& d, int& i, int stride, bool up, int lane) {
    float od = __shfl_xor_sync(FULLMASK, d, stride);
    int   oi = __shfl_xor_sync(FULLMASK, i, stride);
    bool otherSmaller = (od < d) || (od == d && oi < i);
    bool lower = ((lane & stride) == 0);
    bool take = (lower == up) ? otherSmaller : !otherSmaller;
    if (take) { d = od; i = oi; }
}
__device__ __forceinline__ void sort32(float& d, int& i, bool asc, int lane) {
#pragma unroll
    for (int k = 2; k <= 32; k <<= 1) {
        bool up = (((lane & k) == 0) == asc);
#pragma unroll
        for (int s = k >> 1; s > 0; s >>= 1) cas_pair(d, i, s, up, lane);
    }
}
__device__ __forceinline__ void merge32(float& d, int& i, int lane) {
#pragma unroll
    for (int s = 16; s > 0; s >>= 1) cas_pair(d, i, s, true, lane);
}

__global__ __launch_bounds__(256) void knn_kernel(const float* __restrict__ xyz) {
    __shared__ float4 sp4[NN];
    int b = blockIdx.x >> 8;
    int nbase = (blockIdx.x & 255) * 8;
    int tid = threadIdx.x;
    for (int i = tid; i < NN; i += 256) {
        const float* p = xyz + ((size_t)b * NN + i) * 3;
        float x = p[0], y = p[1], z = p[2];
        sp4[i] = make_float4(x, y, z, x * x + y * y + z * z);
    }
    __syncthreads();
    int w = tid >> 5, lane = tid & 31;
    int n = nbase + w;
    float4 qp = sp4[n];

    int j = lane;
    float4 t0 = sp4[j];
    float d = fmaf(-2.f, qp.x * t0.x + qp.y * t0.y + qp.z * t0.z, qp.w + t0.w);
    int di = j;
    sort32(d, di, true, lane);

    for (int c = 1; c < 64; c++) {
        j = c * 32 + lane;
        float4 t = sp4[j];
        float cd = fmaf(-2.f, qp.x * t.x + qp.y * t.y + qp.z * t.z, qp.w + t.w);
        int ci = j;
        float kmax = __shfl_sync(FULLMASK, d, 31);
        if (__any_sync(FULLMASK, cd < kmax)) {
            sort32(cd, ci, false, lane);
            bool less = (cd < d) || (cd == d && ci < di);
            if (less) { d = cd; di = ci; }
            merge32(d, di, lane);
        }
    }
    g_idx[((size_t)b * NN + n) * KK + lane] = di;
}

// ---------------- statsA: h1 stats on the fly ----------------
__global__ __launch_bounds__(256) void statsA_kernel(const float* __restrict__ xyz,
                                                     const float* __restrict__ W1,
                                                     const float* __restrict__ b1) {
    float s[32], s2[32];
#pragma unroll
    for (int c = 0; c < 32; c++) { s[c] = 0.f; s2[c] = 0.f; }
    int tid = threadIdx.x;
    int t0 = blockIdx.x * 256 + tid;
    float rx[4], ry[4], rz[4];
#pragma unroll
    for (int i = 0; i < 4; i++) {
        int r = t0 + i * 65536;
        int b = r >> 16, n = (r >> 5) & 2047, m = g_idx[r];
        const float* pc = xyz + (size_t)((b << 11) + n) * 3;
        const float* pn = xyz + (size_t)((b << 11) + m) * 3;
        rx[i] = pn[0] - pc[0]; ry[i] = pn[1] - pc[1]; rz[i] = pn[2] - pc[2];
    }
#pragma unroll
    for (int c = 0; c < 32; c++) {
        float w0 = __ldg(W1 + c), w1 = __ldg(W1 + 32 + c), w2 = __ldg(W1 + 64 + c), bb = __ldg(b1 + c);
#pragma unroll
        for (int i = 0; i < 4; i++) {
            float z = fmaf(rx[i], w0, fmaf(ry[i], w1, fmaf(rz[i], w2, bb)));
            float v = fmaxf(z, 0.f);
            s[c] += v; s2[c] = fmaf(v, v, s2[c]);
        }
    }
    int lane = tid & 31, w = tid >> 5;
    tr32(s, lane); tr32(s2, lane);
    __shared__ float red[2][8][32];
    red[0][w][lane] = s[0]; red[1][w][lane] = s2[0];
    __syncthreads();
    if (tid < 32) {
        float a = 0.f, a2 = 0.f;
#pragma unroll
        for (int ww = 0; ww < 8; ww++) { a += red[0][ww][tid]; a2 += red[1][ww][tid]; }
        g_ps [tid * 256 + blockIdx.x] = a;
        g_ps2[tid * 256 + blockIdx.x] = a2;
    }
}

// ---------------- fin1: BN1 folded into W2f/b2f ----------------
__global__ __launch_bounds__(1024) void fin1_kernel(const float* __restrict__ g1,
                                                    const float* __restrict__ be1,
                                                    const float* __restrict__ W2,
                                                    const float* __restrict__ b2) {
    __shared__ float ssc[32], ssh[32];
    int tid = threadIdx.x, w = tid >> 5, l = tid & 31;
    float s = 0.f, s2 = 0.f;
#pragma unroll
    for (int i = l; i < 256; i += 32) { s += g_ps[w * 256 + i]; s2 += g_ps2[w * 256 + i]; }
#pragma unroll
    for (int o = 16; o >= 1; o >>= 1) {
        s  += __shfl_down_sync(FULLMASK, s, o);
        s2 += __shfl_down_sync(FULLMASK, s2, o);
    }
    if (l == 0) {
        const float invc = 1.f / (float)RTOT;
        float mean = s * invc;
        float var  = s2 * invc - mean * mean;
        float iv = rsqrtf(var + EPS);
        float sc = g1[w] * iv;
        ssc[w] = sc;
        ssh[w] = fmaf(-mean, sc, be1[w]);
    }
    __syncthreads();
    g_W2f[tid] = ssc[tid >> 5] * W2[tid];
    float v = ssh[l] * W2[l * 32 + w];
#pragma unroll
    for (int o = 16; o >= 1; o >>= 1) v += __shfl_down_sync(FULLMASK, v, o);
    if (l == 0) g_b2f[w] = b2[w] + v;
}

// ---------------- generic finalize ----------------
__global__ __launch_bounds__(1024) void fin_kernel(int G, float invc,
                                                   const float* __restrict__ gamma,
                                                   const float* __restrict__ beta,
                                                   float* __restrict__ scsh) {
    int tid = threadIdx.x, w = tid >> 5, l = tid & 31;
    float s = 0.f, s2 = 0.f;
    for (int i = l; i < G; i += 32) { s += g_ps[w * G + i]; s2 += g_ps2[w * G + i]; }
#pragma unroll
    for (int o = 16; o >= 1; o >>= 1) {
        s  += __shfl_down_sync(FULLMASK, s, o);
        s2 += __shfl_down_sync(FULLMASK, s2, o);
    }
    if (l == 0) {
        float mean = s * invc;
        float var  = s2 * invc - mean * mean;
        float iv = rsqrtf(var + EPS);
        float sc = gamma[w] * iv;
        scsh[w]      = sc;
        scsh[32 + w] = fmaf(-mean, sc, beta[w]);
    }
}

// ---------------- stage2: 2 rows/thread; h recomputed in j-loop; W2 row via LDS.128 ----------------
__global__ __launch_bounds__(256) void stage2_kernel(const float* __restrict__ xyz,
                                                     const float* __restrict__ W1,
                                                     const float* __restrict__ b1) {
    __shared__ __align__(16) float sW2f[1024];
    __shared__ float sb2f[32];
    __shared__ float sW1[96], sb1[32];
    __shared__ float red[2][8][32];
    int tid = threadIdx.x;
    ((float4*)sW2f)[tid] = ((const float4*)g_W2f)[tid & 255];
    if (tid < 96) sW1[tid] = W1[tid];
    else if (tid < 128) sb1[tid - 96] = b1[tid - 96];
    else if (tid < 160) sb2f[tid - 128] = g_b2f[tid - 128];
    __syncthreads();

    int rA = blockIdx.x * 256 + tid;          // [0, 131072)
    int rB = rA + 131072;
    int bA = rA >> 16, nA = (rA >> 5) & 2047, mA = g_idx[rA];
    int bB = rB >> 16, nB = (rB >> 5) & 2047, mB = g_idx[rB];
    const float* pcA = xyz + (size_t)((bA << 11) + nA) * 3;
    const float* pnA = xyz + (size_t)((bA << 11) + mA) * 3;
    const float* pcB = xyz + (size_t)((bB << 11) + nB) * 3;
    const float* pnB = xyz + (size_t)((bB << 11) + mB) * 3;
    float rxA = pnA[0] - pcA[0], ryA = pnA[1] - pcA[1], rzA = pnA[2] - pcA[2];
    float rxB = pnB[0] - pcB[0], ryB = pnB[1] - pcB[1], rzB = pnB[2] - pcB[2];

    unsigned long long accA[16], accB[16];
#pragma unroll
    for (int q = 0; q < 16; q++) {
        unsigned long long bb = pack2(sb2f[2 * q], sb2f[2 * q + 1]);
        accA[q] = bb; accB[q] = bb;
    }
    const unsigned long long* w2p = (const unsigned long long*)sW2f;
#pragma unroll
    for (int j = 0; j < 32; j++) {
        float hA = fmaxf(fmaf(rxA, sW1[j], fmaf(ryA, sW1[32 + j], fmaf(rzA, sW1[64 + j], sb1[j]))), 0.f);
        float hB = fmaxf(fmaf(rxB, sW1[j], fmaf(ryB, sW1[32 + j], fmaf(rzB, sW1[64 + j], sb1[j]))), 0.f);
        unsigned long long hvA = pack2(hA, hA);
        unsigned long long hvB = pack2(hB, hB);
        const unsigned long long* row = w2p + j * 16;
#pragma unroll
        for (int q = 0; q < 16; q++) {
            unsigned long long wv = row[q];   // LDS.128 pairs (compiler vectorizes adjacent)
            accA[q] = ffma2(hvA, wv, accA[q]);
            accB[q] = ffma2(hvB, wv, accB[q]);
        }
    }

    float vA[32], vB[32];
#pragma unroll
    for (int q = 0; q < 16; q++) {
        float2 pA = unpack2(accA[q]);
        float2 pB = unpack2(accB[q]);
        vA[2 * q] = fmaxf(pA.x, 0.f); vA[2 * q + 1] = fmaxf(pA.y, 0.f);
        vB[2 * q] = fmaxf(pB.x, 0.f); vB[2 * q + 1] = fmaxf(pB.y, 0.f);
    }
    float4* oA = (float4*)(g_h2 + (size_t)rA * 32);
    float4* oB = (float4*)(g_h2 + (size_t)rB * 32);
#pragma unroll
    for (int q = 0; q < 8; q++) {
        oA[q] = make_float4(vA[4 * q], vA[4 * q + 1], vA[4 * q + 2], vA[4 * q + 3]);
        oB[q] = make_float4(vB[4 * q], vB[4 * q + 1], vB[4 * q + 2], vB[4 * q + 3]);
    }

    float s[32], s2[32];
#pragma unroll
    for (int c = 0; c < 32; c++) {
        s[c]  = vA[c] + vB[c];
        s2[c] = fmaf(vA[c], vA[c], vB[c] * vB[c]);
    }
    int lane = tid & 31, w = tid >> 5;
    tr32(s, lane); tr32(s2, lane);
    red[0][w][lane] = s[0]; red[1][w][lane] = s2[0];
    __syncthreads();
    if (tid < 32) {
        float a = 0.f, a2 = 0.f;
#pragma unroll
        for (int ww = 0; ww < 8; ww++) { a += red[0][ww][tid]; a2 += red[1][ww][tid]; }
        g_ps [tid * 512 + blockIdx.x] = a;
        g_ps2[tid * 512 + blockIdx.x] = a2;
    }
}

// ---------------- qcompute: Qh[m][o][jp] (jp-contiguous, padded to 20) ----------------
__global__ __launch_bounds__(256) void qcompute_kernel(const float* __restrict__ points,
                                                       const float* __restrict__ W3,
                                                       const float* __restrict__ b3) {
    __shared__ float sp[8][16];
    __shared__ float ssc[32], ssh[32];
    __shared__ float r16p[8][8][32];            // [jg][m][o]
    __shared__ __align__(16) __half2 sQ[8][32][QJP];  // 20 KB staging
    int tid = threadIdx.x;
    int mg0 = blockIdx.x * 8;
    if (tid < 128) sp[tid >> 4][tid & 15] = points[(size_t)(mg0 + (tid >> 4)) * CIN + (tid & 15)];
    else if (tid < 160) { ssc[tid - 128] = g_sc2[tid - 128]; ssh[tid - 128] = g_sc2[32 + tid - 128]; }
    __syncthreads();

    int o = tid & 31, jg = tid >> 5, j0 = jg * 4;
    float acc[8][4];
#pragma unroll
    for (int m = 0; m < 8; m++)
#pragma unroll
        for (int jj = 0; jj < 4; jj++) acc[m][jj] = 0.f;

#pragma unroll
    for (int c = 0; c < 16; c++) {
        float w0 = __ldg(W3 + (size_t)(j0 + 0) * 512 + c * 32 + o);
        float w1 = __ldg(W3 + (size_t)(j0 + 1) * 512 + c * 32 + o);
        float w2 = __ldg(W3 + (size_t)(j0 + 2) * 512 + c * 32 + o);
        float w3 = __ldg(W3 + (size_t)(j0 + 3) * 512 + c * 32 + o);
#pragma unroll
        for (int m = 0; m < 8; m++) {
            float pm = sp[m][c];
            acc[m][0] = fmaf(pm, w0, acc[m][0]);
            acc[m][1] = fmaf(pm, w1, acc[m][1]);
            acc[m][2] = fmaf(pm, w2, acc[m][2]);
            acc[m][3] = fmaf(pm, w3, acc[m][3]);
        }
    }
    float c0 = ssc[j0], c1 = ssc[j0 + 1], c2 = ssc[j0 + 2], c3 = ssc[j0 + 3];
    float h0 = ssh[j0], h1 = ssh[j0 + 1], h2v = ssh[j0 + 2], h3 = ssh[j0 + 3];
#pragma unroll
    for (int m = 0; m < 8; m++) {
        sQ[m][o][jg * 2]     = __floats2half2_rn(acc[m][0] * c0, acc[m][1] * c1);
        sQ[m][o][jg * 2 + 1] = __floats2half2_rn(acc[m][2] * c2, acc[m][3] * c3);
        r16p[jg][m][o] = fmaf(h0, acc[m][0], fmaf(h1, acc[m][1], fmaf(h2v, acc[m][2], h3 * acc[m][3])));
    }
    __syncthreads();
    {
        int m = tid >> 5;
        float sum = 0.f;
#pragma unroll
        for (int g = 0; g < 8; g++) sum += r16p[g][m][o];
        float pb = 0.f;
#pragma unroll
        for (int c = 0; c < 16; c++) pb = fmaf(sp[m][c], __ldg(b3 + c * 32 + o), pb);
        sQ[m][o][16] = __floats2half2_rn(sum + pb, 0.f);
        sQ[m][o][17] = __floats2half2_rn(0.f, 0.f);
        sQ[m][o][18] = __floats2half2_rn(0.f, 0.f);
        sQ[m][o][19] = __floats2half2_rn(0.f, 0.f);
    }
    __syncthreads();
    // coalesced copy out: 8*32*20 half2 = 1280 uint4
    const uint4* src = (const uint4*)&sQ[0][0][0];
    uint4* dst = (uint4*)(g_Qh + (size_t)mg0 * QROW);
#pragma unroll
    for (int t = 0; t < 5; t++) dst[tid + t * 256] = src[tid + t * 256];
}

// ---------------- stage3 ----------------
__global__ __launch_bounds__(256) void stage3_kernel(float* __restrict__ out) {
    __shared__ float2 sH[32 * 17];
    __shared__ int sidx[32];
    __shared__ float wmax[8][32];
    int tid = threadIdx.x;
    int q = blockIdx.x;
    size_t r0 = (size_t)q * KK;
    if (tid < 32) sidx[tid] = g_idx[r0 + tid];
    for (int t = tid; t < 512; t += 256) {
        int k = t >> 4, jp = t & 15;
        sH[k * 17 + jp] = ((const float2*)(g_h2 + (r0 + k) * 32))[jp];
    }
    if (tid < 32) sH[tid * 17 + 16] = make_float2(1.f, 0.f);
    __syncthreads();

    int w = tid >> 5, o = tid & 31, b = q >> 11;
    float vmax = -3.4e38f;
#pragma unroll
    for (int kk = 0; kk < 4; kk++) {
        int k = w + kk * 8;
        int m = sidx[k];
        const __half2* Qp = g_Qh + (size_t)((b << 11) + m) * QROW + o * QJP;
        uint4 u0 = *(const uint4*)(Qp + 0);
        uint4 u1 = *(const uint4*)(Qp + 4);
        uint4 u2 = *(const uint4*)(Qp + 8);
        uint4 u3 = *(const uint4*)(Qp + 12);
        unsigned int u4 = *(const unsigned int*)(Qp + 16);
        unsigned int qv[17] = {u0.x, u0.y, u0.z, u0.w, u1.x, u1.y, u1.z, u1.w,
                               u2.x, u2.y, u2.z, u2.w, u3.x, u3.y, u3.z, u3.w, u4};
        float acc = 0.f;
#pragma unroll
        for (int jp = 0; jp < 17; jp++) {
            float2 hv = sH[k * 17 + jp];
            float2 qf = __half22float2(*(const __half2*)&qv[jp]);
            acc = fmaf(hv.x, qf.x, fmaf(hv.y, qf.y, acc));
        }
        vmax = fmaxf(vmax, acc);
    }
    wmax[w][o] = vmax;
    __syncthreads();
    if (tid < 32) {
        float v = wmax[0][tid];
#pragma unroll
        for (int i = 1; i < 8; i++) v = fmaxf(v, wmax[i][tid]);
        out[(size_t)q * 32 + tid] = v;
    }
}

// ---------------- statsC ----------------
__global__ __launch_bounds__(256) void statsC_kernel(const float* __restrict__ out) {
    int tid = threadIdx.x;
    int q = blockIdx.x * 256 + tid;
    float v[32], s2[32];
    const float4* p = (const float4*)(out + (size_t)q * 32);
#pragma unroll
    for (int i = 0; i < 8; i++) {
        float4 x = p[i];
        v[4 * i] = x.x; v[4 * i + 1] = x.y; v[4 * i + 2] = x.z; v[4 * i + 3] = x.w;
    }
#pragma unroll
    for (int c = 0; c < 32; c++) s2[c] = v[c] * v[c];
    int lane = tid & 31, w = tid >> 5;
    tr32(v, lane); tr32(s2, lane);
    __shared__ float red[2][8][32];
    red[0][w][lane] = v[0]; red[1][w][lane] = s2[0];
    __syncthreads();
    if (tid < 32) {
        float a = 0.f, a2 = 0.f;
#pragma unroll
        for (int ww = 0; ww < 8; ww++) { a += red[0][ww][tid]; a2 += red[1][ww][tid]; }
        g_ps [tid * 32 + blockIdx.x] = a;
        g_ps2[tid * 32 + blockIdx.x] = a2;
    }
}

// ---------------- final BN in place ----------------
__global__ __launch_bounds__(256) void finalbn_kernel(float* __restrict__ out) {
    int e = blockIdx.x * 256 + threadIdx.x;
    float4 v = ((float4*)out)[e];
    int c = (e * 4) & 31;
    v.x = fmaf(v.x, g_sc3[c],     g_sc3[32 + c]);
    v.y = fmaf(v.y, g_sc3[c + 1], g_sc3[33 + c]);
    v.z = fmaf(v.z, g_sc3[c + 2], g_sc3[34 + c]);
    v.w = fmaf(v.w, g_sc3[c + 3], g_sc3[35 + c]);
    ((float4*)out)[e] = v;
}

// ---------------- launcher ----------------
extern "C" void kernel_launch(void* const* d_in, const int* in_sizes, int n_in,
                              void* d_out, int out_size) {
    const float* xyz    = (const float*)d_in[0];
    const float* points = (const float*)d_in[1];
    const float* W1     = (const float*)d_in[2];
    const float* b1     = (const float*)d_in[3];
    const float* g1     = (const float*)d_in[4];
    const float* be1    = (const float*)d_in[5];
    const float* W2     = (const float*)d_in[6];
    const float* b2     = (const float*)d_in[7];
    const float* g2     = (const float*)d_in[8];
    const float* be2    = (const float*)d_in[9];
    const float* W3     = (const float*)d_in[10];
    const float* b3     = (const float*)d_in[11];
    const float* gbn    = (const float*)d_in[12];
    const float* bbn    = (const float*)d_in[13];
    float* out = (float*)d_out;

    float* p_sc2; cudaGetSymbolAddress((void**)&p_sc2, g_sc2);
    float* p_sc3; cudaGetSymbolAddress((void**)&p_sc3, g_sc3);

    knn_kernel   <<<1024, 256>>>(xyz);
    statsA_kernel<<<256, 256>>>(xyz, W1, b1);
    fin1_kernel  <<<1, 1024>>>(g1, be1, W2, b2);
    stage2_kernel<<<512, 256>>>(xyz, W1, b1);
    fin_kernel   <<<1, 1024>>>(512, 1.f / (float)RTOT, g2, be2, p_sc2);
    qcompute_kernel<<<MTOT / 8, 256>>>(points, W3, b3);
    stage3_kernel<<<MTOT, 256>>>(out);
    statsC_kernel<<<32, 256>>>(out);
    fin_kernel   <<<1, 1024>>>(32, 1.f / (float)MTOT, gbn, bbn, p_sc3);
    finalbn_kernel<<<256, 256>>>(out);
}

// round 4
// speedup vs baseline: 1.8851x; 1.8851x over previous
#include <cuda_runtime.h>
#include <cuda_fp16.h>
#include <cstdint>

#define BB 4
#define NN 2048
#define KK 32
#define CIN 16
#define COUT 32
#define HH 32
#define RTOT (BB*NN*KK)      // 262144
#define MTOT (BB*NN)         // 8192
#define EPS 1e-5f
#define FULLMASK 0xffffffffu

// Q layout: [m][jg=0..8][o] as uint2 (two half2 = jp pair). Coalesced per warp (lane=o).
#define QJG 9
#define QSTRIDE (QJG*32)     // uint2 per m

// ---------------- scratch ----------------
__device__ __align__(16) float g_h2[(size_t)RTOT*HH];        // 32 MB (pre-BN2 h2)
__device__ __align__(16) uint2 g_Q2[(size_t)MTOT*QSTRIDE];   // 18.9 MB
__device__ int   g_idx[RTOT];
__device__ float g_ps [32*1024];
__device__ float g_ps2[32*1024];
__device__ float g_sc2[64];
__device__ float g_sc3[64];
__device__ __align__(16) float g_W2f[1024];   // sc1-folded W2
__device__ float g_b2f[32];                   // sh1-folded b2

// ---------------- helpers ----------------
__device__ __forceinline__ unsigned long long pack2(float x, float y) {
    unsigned long long r;
    asm("mov.b64 %0, {%1,%2};" : "=l"(r) : "f"(x), "f"(y));
    return r;
}
__device__ __forceinline__ float2 unpack2(unsigned long long v) {
    float2 r;
    asm("mov.b64 {%0,%1}, %2;" : "=f"(r.x), "=f"(r.y) : "l"(v));
    return r;
}
__device__ __forceinline__ unsigned long long ffma2(unsigned long long a, unsigned long long b, unsigned long long c) {
    unsigned long long d;
    asm("fma.rn.f32x2 %0, %1, %2, %3;" : "=l"(d) : "l"(a), "l"(b), "l"(c));
    return d;
}

// warp transpose-reduce
__device__ __forceinline__ void tr32(float (&acc)[32], int lane) {
#pragma unroll
    for (int s = 16; s >= 1; s >>= 1) {
#pragma unroll
        for (int i = 0; i < s; i++) {
            float a0 = acc[i], a1 = acc[i + s];
            float give = (lane & s) ? a0 : a1;
            float keep = (lane & s) ? a1 : a0;
            acc[i] = keep + __shfl_xor_sync(FULLMASK, give, s);
        }
    }
}

// ---------------- KNN: bitonic init + ballot/insertion stream ----------------
__device__ __forceinline__ void cas_pair(float& d, int& i, int stride, bool up, int lane) {
    float od = __shfl_xor_sync(FULLMASK, d, stride);
    int   oi = __shfl_xor_sync(FULLMASK, i, stride);
    bool otherSmaller = (od < d) || (od == d && oi < i);
    bool lower = ((lane & stride) == 0);
    bool take = (lower == up) ? otherSmaller : !otherSmaller;
    if (take) { d = od; i = oi; }
}
__device__ __forceinline__ void sort32(float& d, int& i, bool asc, int lane) {
#pragma unroll
    for (int k = 2; k <= 32; k <<= 1) {
        bool up = (((lane & k) == 0) == asc);
#pragma unroll
        for (int s = k >> 1; s > 0; s >>= 1) cas_pair(d, i, s, up, lane);
    }
}

__global__ __launch_bounds__(256) void knn_kernel(const float* __restrict__ xyz) {
    __shared__ float4 sp4[NN];
    int b = blockIdx.x >> 8;
    int nbase = (blockIdx.x & 255) * 8;
    int tid = threadIdx.x;
    for (int i = tid; i < NN; i += 256) {
        const float* p = xyz + ((size_t)b * NN + i) * 3;
        float x = p[0], y = p[1], z = p[2];
        sp4[i] = make_float4(x, y, z, x * x + y * y + z * z);
    }
    __syncthreads();
    int w = tid >> 5, lane = tid & 31;
    int n = nbase + w;
    float4 qp = sp4[n];

    // chunk 0: bitonic sort ascending (by (d, idx))
    float4 t0 = sp4[lane];
    float d = fmaf(-2.f, qp.x * t0.x + qp.y * t0.y + qp.z * t0.z, qp.w + t0.w);
    int di = lane;
    sort32(d, di, true, lane);
    float kmax = __shfl_sync(FULLMASK, d, 31);

    for (int c = 1; c < 64; c++) {
        int j = c * 32 + lane;
        float4 t = sp4[j];
        float cd = fmaf(-2.f, qp.x * t.x + qp.y * t.y + qp.z * t.z, qp.w + t.w);
        unsigned mask = __ballot_sync(FULLMASK, cd < kmax);
        while (mask) {
            int src = __ffs(mask) - 1;
            mask &= mask - 1;
            float v = __shfl_sync(FULLMASK, cd, src);
            if (v >= kmax) continue;                     // list shrank since ballot
            int vi = c * 32 + src;
            // sorted-ascending insert: existing equal values have lower index -> count d<=v
            unsigned le = __ballot_sync(FULLMASK, d <= v);
            int pos = __popc(le);                        // pos <= 31 since v < d[31]
            float ds = __shfl_up_sync(FULLMASK, d, 1);
            int   is = __shfl_up_sync(FULLMASK, di, 1);
            if (lane == pos)      { d = v;  di = vi; }
            else if (lane > pos)  { d = ds; di = is; }
            kmax = __shfl_sync(FULLMASK, d, 31);
        }
    }
    g_idx[((size_t)b * NN + n) * KK + lane] = di;
}

// ---------------- statsA: h1 stats on the fly ----------------
__global__ __launch_bounds__(256) void statsA_kernel(const float* __restrict__ xyz,
                                                     const float* __restrict__ W1,
                                                     const float* __restrict__ b1) {
    float s[32], s2[32];
#pragma unroll
    for (int c = 0; c < 32; c++) { s[c] = 0.f; s2[c] = 0.f; }
    int tid = threadIdx.x;
    int t0 = blockIdx.x * 256 + tid;
    float rx[4], ry[4], rz[4];
#pragma unroll
    for (int i = 0; i < 4; i++) {
        int r = t0 + i * 65536;
        int b = r >> 16, n = (r >> 5) & 2047, m = g_idx[r];
        const float* pc = xyz + (size_t)((b << 11) + n) * 3;
        const float* pn = xyz + (size_t)((b << 11) + m) * 3;
        rx[i] = pn[0] - pc[0]; ry[i] = pn[1] - pc[1]; rz[i] = pn[2] - pc[2];
    }
#pragma unroll
    for (int c = 0; c < 32; c++) {
        float w0 = __ldg(W1 + c), w1 = __ldg(W1 + 32 + c), w2 = __ldg(W1 + 64 + c), bb = __ldg(b1 + c);
#pragma unroll
        for (int i = 0; i < 4; i++) {
            float z = fmaf(rx[i], w0, fmaf(ry[i], w1, fmaf(rz[i], w2, bb)));
            float v = fmaxf(z, 0.f);
            s[c] += v; s2[c] = fmaf(v, v, s2[c]);
        }
    }
    int lane = tid & 31, w = tid >> 5;
    tr32(s, lane); tr32(s2, lane);
    __shared__ float red[2][8][32];
    red[0][w][lane] = s[0]; red[1][w][lane] = s2[0];
    __syncthreads();
    if (tid < 32) {
        float a = 0.f, a2 = 0.f;
#pragma unroll
        for (int ww = 0; ww < 8; ww++) { a += red[0][ww][tid]; a2 += red[1][ww][tid]; }
        g_ps [tid * 256 + blockIdx.x] = a;
        g_ps2[tid * 256 + blockIdx.x] = a2;
    }
}

// ---------------- fin1: BN1 folded into W2f/b2f ----------------
__global__ __launch_bounds__(1024) void fin1_kernel(const float* __restrict__ g1,
                                                    const float* __restrict__ be1,
                                                    const float* __restrict__ W2,
                                                    const float* __restrict__ b2) {
    __shared__ float ssc[32], ssh[32];
    int tid = threadIdx.x, w = tid >> 5, l = tid & 31;
    float s = 0.f, s2 = 0.f;
#pragma unroll
    for (int i = l; i < 256; i += 32) { s += g_ps[w * 256 + i]; s2 += g_ps2[w * 256 + i]; }
#pragma unroll
    for (int o = 16; o >= 1; o >>= 1) {
        s  += __shfl_down_sync(FULLMASK, s, o);
        s2 += __shfl_down_sync(FULLMASK, s2, o);
    }
    if (l == 0) {
        const float invc = 1.f / (float)RTOT;
        float mean = s * invc;
        float var  = s2 * invc - mean * mean;
        float iv = rsqrtf(var + EPS);
        float sc = g1[w] * iv;
        ssc[w] = sc;
        ssh[w] = fmaf(-mean, sc, be1[w]);
    }
    __syncthreads();
    g_W2f[tid] = ssc[tid >> 5] * W2[tid];
    float v = ssh[l] * W2[l * 32 + w];
#pragma unroll
    for (int o = 16; o >= 1; o >>= 1) v += __shfl_down_sync(FULLMASK, v, o);
    if (l == 0) g_b2f[w] = b2[w] + v;
}

// ---------------- generic finalize ----------------
__global__ __launch_bounds__(1024) void fin_kernel(int G, float invc,
                                                   const float* __restrict__ gamma,
                                                   const float* __restrict__ beta,
                                                   float* __restrict__ scsh) {
    int tid = threadIdx.x, w = tid >> 5, l = tid & 31;
    float s = 0.f, s2 = 0.f;
    for (int i = l; i < G; i += 32) { s += g_ps[w * G + i]; s2 += g_ps2[w * G + i]; }
#pragma unroll
    for (int o = 16; o >= 1; o >>= 1) {
        s  += __shfl_down_sync(FULLMASK, s, o);
        s2 += __shfl_down_sync(FULLMASK, s2, o);
    }
    if (l == 0) {
        float mean = s * invc;
        float var  = s2 * invc - mean * mean;
        float iv = rsqrtf(var + EPS);
        float sc = gamma[w] * iv;
        scsh[w]      = sc;
        scsh[32 + w] = fmaf(-mean, sc, beta[w]);
    }
}

// ---------------- stage2: 2 rows/thread (R3 version, kept) ----------------
__global__ __launch_bounds__(256) void stage2_kernel(const float* __restrict__ xyz,
                                                     const float* __restrict__ W1,
                                                     const float* __restrict__ b1) {
    __shared__ __align__(16) float sW2f[1024];
    __shared__ float sb2f[32];
    __shared__ float sW1[96], sb1[32];
    __shared__ float red[2][8][32];
    int tid = threadIdx.x;
    ((float4*)sW2f)[tid] = ((const float4*)g_W2f)[tid & 255];
    if (tid < 96) sW1[tid] = W1[tid];
    else if (tid < 128) sb1[tid - 96] = b1[tid - 96];
    else if (tid < 160) sb2f[tid - 128] = g_b2f[tid - 128];
    __syncthreads();

    int rA = blockIdx.x * 256 + tid;
    int rB = rA + 131072;
    int bA = rA >> 16, nA = (rA >> 5) & 2047, mA = g_idx[rA];
    int bB = rB >> 16, nB = (rB >> 5) & 2047, mB = g_idx[rB];
    const float* pcA = xyz + (size_t)((bA << 11) + nA) * 3;
    const float* pnA = xyz + (size_t)((bA << 11) + mA) * 3;
    const float* pcB = xyz + (size_t)((bB << 11) + nB) * 3;
    const float* pnB = xyz + (size_t)((bB << 11) + mB) * 3;
    float rxA = pnA[0] - pcA[0], ryA = pnA[1] - pcA[1], rzA = pnA[2] - pcA[2];
    float rxB = pnB[0] - pcB[0], ryB = pnB[1] - pcB[1], rzB = pnB[2] - pcB[2];

    unsigned long long accA[16], accB[16];
#pragma unroll
    for (int q = 0; q < 16; q++) {
        unsigned long long bb = pack2(sb2f[2 * q], sb2f[2 * q + 1]);
        accA[q] = bb; accB[q] = bb;
    }
    const unsigned long long* w2p = (const unsigned long long*)sW2f;
#pragma unroll
    for (int j = 0; j < 32; j++) {
        float hA = fmaxf(fmaf(rxA, sW1[j], fmaf(ryA, sW1[32 + j], fmaf(rzA, sW1[64 + j], sb1[j]))), 0.f);
        float hB = fmaxf(fmaf(rxB, sW1[j], fmaf(ryB, sW1[32 + j], fmaf(rzB, sW1[64 + j], sb1[j]))), 0.f);
        unsigned long long hvA = pack2(hA, hA);
        unsigned long long hvB = pack2(hB, hB);
        const unsigned long long* row = w2p + j * 16;
#pragma unroll
        for (int q = 0; q < 16; q++) {
            unsigned long long wv = row[q];
            accA[q] = ffma2(hvA, wv, accA[q]);
            accB[q] = ffma2(hvB, wv, accB[q]);
        }
    }

    float vA[32], vB[32];
#pragma unroll
    for (int q = 0; q < 16; q++) {
        float2 pA = unpack2(accA[q]);
        float2 pB = unpack2(accB[q]);
        vA[2 * q] = fmaxf(pA.x, 0.f); vA[2 * q + 1] = fmaxf(pA.y, 0.f);
        vB[2 * q] = fmaxf(pB.x, 0.f); vB[2 * q + 1] = fmaxf(pB.y, 0.f);
    }
    float4* oA = (float4*)(g_h2 + (size_t)rA * 32);
    float4* oB = (float4*)(g_h2 + (size_t)rB * 32);
#pragma unroll
    for (int q = 0; q < 8; q++) {
        oA[q] = make_float4(vA[4 * q], vA[4 * q + 1], vA[4 * q + 2], vA[4 * q + 3]);
        oB[q] = make_float4(vB[4 * q], vB[4 * q + 1], vB[4 * q + 2], vB[4 * q + 3]);
    }

    float s[32], s2[32];
#pragma unroll
    for (int c = 0; c < 32; c++) {
        s[c]  = vA[c] + vB[c];
        s2[c] = fmaf(vA[c], vA[c], vB[c] * vB[c]);
    }
    int lane = tid & 31, w = tid >> 5;
    tr32(s, lane); tr32(s2, lane);
    red[0][w][lane] = s[0]; red[1][w][lane] = s2[0];
    __syncthreads();
    if (tid < 32) {
        float a = 0.f, a2 = 0.f;
#pragma unroll
        for (int ww = 0; ww < 8; ww++) { a += red[0][ww][tid]; a2 += red[1][ww][tid]; }
        g_ps [tid * 512 + blockIdx.x] = a;
        g_ps2[tid * 512 + blockIdx.x] = a2;
    }
}

// ---------------- qcompute: Q2[m][jg][o] = uint2(half2 pair), direct coalesced stores ----------------
__global__ __launch_bounds__(256) void qcompute_kernel(const float* __restrict__ points,
                                                       const float* __restrict__ W3,
                                                       const float* __restrict__ b3) {
    __shared__ float sp[8][16];
    __shared__ float ssc[32], ssh[32];
    __shared__ float r16p[8][8][32];   // [jg][m][o]
    int tid = threadIdx.x;
    int mg0 = blockIdx.x * 8;
    if (tid < 128) sp[tid >> 4][tid & 15] = points[(size_t)(mg0 + (tid >> 4)) * CIN + (tid & 15)];
    else if (tid < 160) { ssc[tid - 128] = g_sc2[tid - 128]; ssh[tid - 128] = g_sc2[32 + tid - 128]; }
    __syncthreads();

    int o = tid & 31, jg = tid >> 5, j0 = jg * 4;
    float acc[8][4];
#pragma unroll
    for (int m = 0; m < 8; m++)
#pragma unroll
        for (int jj = 0; jj < 4; jj++) acc[m][jj] = 0.f;

#pragma unroll
    for (int c = 0; c < 16; c++) {
        float w0 = __ldg(W3 + (size_t)(j0 + 0) * 512 + c * 32 + o);
        float w1 = __ldg(W3 + (size_t)(j0 + 1) * 512 + c * 32 + o);
        float w2 = __ldg(W3 + (size_t)(j0 + 2) * 512 + c * 32 + o);
        float w3 = __ldg(W3 + (size_t)(j0 + 3) * 512 + c * 32 + o);
#pragma unroll
        for (int m = 0; m < 8; m++) {
            float pm = sp[m][c];
            acc[m][0] = fmaf(pm, w0, acc[m][0]);
            acc[m][1] = fmaf(pm, w1, acc[m][1]);
            acc[m][2] = fmaf(pm, w2, acc[m][2]);
            acc[m][3] = fmaf(pm, w3, acc[m][3]);
        }
    }
    float c0 = ssc[j0], c1 = ssc[j0 + 1], c2 = ssc[j0 + 2], c3 = ssc[j0 + 3];
    float h0 = ssh[j0], h1 = ssh[j0 + 1], h2v = ssh[j0 + 2], h3 = ssh[j0 + 3];
#pragma unroll
    for (int m = 0; m < 8; m++) {
        __half2 p0 = __floats2half2_rn(acc[m][0] * c0, acc[m][1] * c1);
        __half2 p1 = __floats2half2_rn(acc[m][2] * c2, acc[m][3] * c3);
        uint2 u;
        u.x = *(const unsigned int*)&p0;
        u.y = *(const unsigned int*)&p1;
        g_Q2[((size_t)(mg0 + m) * QJG + jg) * 32 + o] = u;
        r16p[jg][m][o] = fmaf(h0, acc[m][0], fmaf(h1, acc[m][1], fmaf(h2v, acc[m][2], h3 * acc[m][3])));
    }
    __syncthreads();
    {
        int m = tid >> 5;
        float sum = 0.f;
#pragma unroll
        for (int g = 0; g < 8; g++) sum += r16p[g][m][o];
        float pb = 0.f;
#pragma unroll
        for (int c = 0; c < 16; c++) pb = fmaf(sp[m][c], __ldg(b3 + c * 32 + o), pb);
        __half2 t = __floats2half2_rn(sum + pb, 0.f);
        uint2 u;
        u.x = *(const unsigned int*)&t;
        u.y = 0u;
        g_Q2[((size_t)(mg0 + m) * QJG + 8) * 32 + o] = u;
    }
}

// ---------------- stage3 ----------------
__global__ __launch_bounds__(256) void stage3_kernel(float* __restrict__ out) {
    __shared__ float2 sH[32 * 18];
    __shared__ int sidx[32];
    __shared__ float wmax[8][32];
    int tid = threadIdx.x;
    int q = blockIdx.x;
    size_t r0 = (size_t)q * KK;
    if (tid < 32) sidx[tid] = g_idx[r0 + tid];
    for (int t = tid; t < 512; t += 256) {
        int k = t >> 4, jp = t & 15;
        sH[k * 18 + jp] = ((const float2*)(g_h2 + (r0 + k) * 32))[jp];
    }
    if (tid < 32) {
        sH[tid * 18 + 16] = make_float2(1.f, 0.f);
        sH[tid * 18 + 17] = make_float2(0.f, 0.f);
    }
    __syncthreads();

    int w = tid >> 5, o = tid & 31, b = q >> 11;
    float vmax = -3.4e38f;
#pragma unroll
    for (int kk = 0; kk < 4; kk++) {
        int k = w + kk * 8;
        int m = sidx[k];
        const uint2* Qp = g_Q2 + (size_t)((b << 11) + m) * QSTRIDE + o;
        const float2* sHk = &sH[k * 18];
        float acc = 0.f;
#pragma unroll
        for (int jg = 0; jg < 9; jg++) {
            uint2 u = Qp[(size_t)jg * 32];
            float2 qa = __half22float2(*(const __half2*)&u.x);
            float2 qb = __half22float2(*(const __half2*)&u.y);
            float2 ha = sHk[jg * 2], hb = sHk[jg * 2 + 1];
            acc = fmaf(ha.x, qa.x, fmaf(ha.y, qa.y, acc));
            acc = fmaf(hb.x, qb.x, fmaf(hb.y, qb.y, acc));
        }
        vmax = fmaxf(vmax, acc);
    }
    wmax[w][o] = vmax;
    __syncthreads();
    if (tid < 32) {
        float v = wmax[0][tid];
#pragma unroll
        for (int i = 1; i < 8; i++) v = fmaxf(v, wmax[i][tid]);
        out[(size_t)q * 32 + tid] = v;
    }
}

// ---------------- statsC ----------------
__global__ __launch_bounds__(256) void statsC_kernel(const float* __restrict__ out) {
    int tid = threadIdx.x;
    int q = blockIdx.x * 256 + tid;
    float v[32], s2[32];
    const float4* p = (const float4*)(out + (size_t)q * 32);
#pragma unroll
    for (int i = 0; i < 8; i++) {
        float4 x = p[i];
        v[4 * i] = x.x; v[4 * i + 1] = x.y; v[4 * i + 2] = x.z; v[4 * i + 3] = x.w;
    }
#pragma unroll
    for (int c = 0; c < 32; c++) s2[c] = v[c] * v[c];
    int lane = tid & 31, w = tid >> 5;
    tr32(v, lane); tr32(s2, lane);
    __shared__ float red[2][8][32];
    red[0][w][lane] = v[0]; red[1][w][lane] = s2[0];
    __syncthreads();
    if (tid < 32) {
        float a = 0.f, a2 = 0.f;
#pragma unroll
        for (int ww = 0; ww < 8; ww++) { a += red[0][ww][tid]; a2 += red[1][ww][tid]; }
        g_ps [tid * 32 + blockIdx.x] = a;
        g_ps2[tid * 32 + blockIdx.x] = a2;
    }
}

// ---------------- final BN in place ----------------
__global__ __launch_bounds__(256) void finalbn_kernel(float* __restrict__ out) {
    int e = blockIdx.x * 256 + threadIdx.x;
    float4 v = ((float4*)out)[e];
    int c = (e * 4) & 31;
    v.x = fmaf(v.x, g_sc3[c],     g_sc3[32 + c]);
    v.y = fmaf(v.y, g_sc3[c + 1], g_sc3[33 + c]);
    v.z = fmaf(v.z, g_sc3[c + 2], g_sc3[34 + c]);
    v.w = fmaf(v.w, g_sc3[c + 3], g_sc3[35 + c]);
    ((float4*)out)[e] = v;
}

// ---------------- launcher ----------------
extern "C" void kernel_launch(void* const* d_in, const int* in_sizes, int n_in,
                              void* d_out, int out_size) {
    const float* xyz    = (const float*)d_in[0];
    const float* points = (const float*)d_in[1];
    const float* W1     = (const float*)d_in[2];
    const float* b1     = (const float*)d_in[3];
    const float* g1     = (const float*)d_in[4];
    const float* be1    = (const float*)d_in[5];
    const float* W2     = (const float*)d_in[6];
    const float* b2     = (const float*)d_in[7];
    const float* g2     = (const float*)d_in[8];
    const float* be2    = (const float*)d_in[9];
    const float* W3     = (const float*)d_in[10];
    const float* b3     = (const float*)d_in[11];
    const float* gbn    = (const float*)d_in[12];
    const float* bbn    = (const float*)d_in[13];
    float* out = (float*)d_out;

    float* p_sc2; cudaGetSymbolAddress((void**)&p_sc2, g_sc2);
    float* p_sc3; cudaGetSymbolAddress((void**)&p_sc3, g_sc3);

    knn_kernel   <<<1024, 256>>>(xyz);
    statsA_kernel<<<256, 256>>>(xyz, W1, b1);
    fin1_kernel  <<<1, 1024>>>(g1, be1, W2, b2);
    stage2_kernel<<<512, 256>>>(xyz, W1, b1);
    fin_kernel   <<<1, 1024>>>(512, 1.f / (float)RTOT, g2, be2, p_sc2);
    qcompute_kernel<<<MTOT / 8, 256>>>(points, W3, b3);
    stage3_kernel<<<MTOT, 256>>>(out);
    statsC_kernel<<<32, 256>>>(out);
    fin_kernel   <<<1, 1024>>>(32, 1.f / (float)MTOT, gbn, bbn, p_sc3);
    finalbn_kernel<<<256, 256>>>(out);
}